// round 15
// baseline (speedup 1.0000x reference)
#include <cuda_runtime.h>
#include <cuda_fp16.h>
#include <math.h>
#include <stdint.h>

// Problem constants
#define SEQ      4096
#define EMB      2048
#define NHEADS   16
#define NKV      4
#define HDIM     128
#define GROUP    (NHEADS / NKV)
#define QKV_N    3072            // 2048 Q + 512 K + 512 V

typedef unsigned long long u64;
typedef unsigned int u32;

// softmax scale folded into Q: 1/sqrt(128) * log2(e)
#define QSCL 0.12753102694420f

// ---------------- scratch (device globals; no allocation allowed) ----------
__device__ __half g_qkvh[SEQ * QKV_N];            // fused projection (half)
__device__ __half g_xh  [SEQ * EMB];
__device__ __half g_qh  [NHEADS * SEQ * HDIM];
__device__ __half g_kh  [NKV * SEQ * HDIM];
__device__ __half g_vh  [NKV * SEQ * HDIM];
__device__ __half g_ctxh[SEQ * NHEADS * HDIM];
__device__ float  g_rcos[SEQ * 64];
__device__ float  g_rsin[SEQ * 64];
__device__ __half g_wqkvt[QKV_N * EMB];           // [3072][2048]
__device__ __half g_wot  [EMB * EMB];

// ---------------- helpers ----------------------------------------------------
__device__ __forceinline__ u32 f2h2(float lo, float hi) {
    __half2 h = __floats2half2_rn(lo, hi);
    return *reinterpret_cast<u32*>(&h);
}
__device__ __forceinline__ void mma_f16(float c[4], uint4 a, u32 b0, u32 b1) {
    asm("mma.sync.aligned.m16n8k16.row.col.f32.f16.f16.f32 "
        "{%0,%1,%2,%3},{%4,%5,%6,%7},{%8,%9},{%0,%1,%2,%3};"
        : "+f"(c[0]), "+f"(c[1]), "+f"(c[2]), "+f"(c[3])
        : "r"(a.x), "r"(a.y), "r"(a.z), "r"(a.w), "r"(b0), "r"(b1));
}
__device__ __forceinline__ u32 smem_u32(const void* p) {
    u32 a;
    asm("{ .reg .u64 t; cvta.to.shared.u64 t, %1; cvt.u32.u64 %0, t; }"
        : "=r"(a) : "l"(p));
    return a;
}
__device__ __forceinline__ void cp16(u32 saddr, const void* gptr) {
    asm volatile("cp.async.cg.shared.global [%0], [%1], 16;"
                 :: "r"(saddr), "l"(gptr) : "memory");
}
#define CP_COMMIT() asm volatile("cp.async.commit_group;" ::: "memory")
#define CP_WAIT(n)  asm volatile("cp.async.wait_group %0;" :: "n"(n) : "memory")

__device__ __forceinline__ void ldsm4(u32 r[4], u32 saddr) {
    asm volatile("ldmatrix.sync.aligned.m8n8.x4.shared.b16 {%0,%1,%2,%3}, [%4];"
                 : "=r"(r[0]), "=r"(r[1]), "=r"(r[2]), "=r"(r[3]) : "r"(saddr));
}
__device__ __forceinline__ void ldsm4t(u32 r[4], u32 saddr) {
    asm volatile("ldmatrix.sync.aligned.m8n8.x4.trans.shared.b16 {%0,%1,%2,%3}, [%4];"
                 : "=r"(r[0]), "=r"(r[1]), "=r"(r[2]), "=r"(r[3]) : "r"(saddr));
}

// ---------------- merged prep kernel ----------------------------------------
#define PREP_BLOCKS (8192 + 6144 + 4096 + 1024)

__global__ void __launch_bounds__(256) prep_kernel(
    const float* __restrict__ x,
    const float* __restrict__ Wq, const float* __restrict__ Wk,
    const float* __restrict__ Wv, const float* __restrict__ Wo,
    const int* __restrict__ pos,
    __half* __restrict__ xh, __half* __restrict__ wqkvt,
    __half* __restrict__ wot)
{
    __shared__ __half t[32][33];
    const int b   = blockIdx.x;
    const int tid = threadIdx.x;

    if (b < 8192) {                                  // x -> half
        const int i = b * 256 + tid;
        float4 v = ((const float4*)x)[i];
        ((uint2*)xh)[i] = make_uint2(f2h2(v.x, v.y), f2h2(v.z, v.w));
        return;
    }
    if (b < 8192 + 6144) {                           // QKV transpose
        const int bb = b - 8192;
        const int n0 = (bb % 96) * 32, k0 = (bb / 96) * 32;
        const int xL = tid & 31, y = tid >> 5;
        const float* src; int N, nl;
        if      (n0 < 2048) { src = Wq; N = 2048; nl = n0; }
        else if (n0 < 2560) { src = Wk; N = 512;  nl = n0 - 2048; }
        else                { src = Wv; N = 512;  nl = n0 - 2560; }
#pragma unroll
        for (int j = 0; j < 4; j++) {
            const int k = y + j * 8;
            t[k][xL] = __float2half_rn(src[(size_t)(k0 + k) * N + nl + xL]);
        }
        __syncthreads();
#pragma unroll
        for (int j = 0; j < 4; j++) {
            const int n = y + j * 8;
            wqkvt[(size_t)(n0 + n) * EMB + k0 + xL] = t[xL][n];
        }
        return;
    }
    if (b < 8192 + 6144 + 4096) {                    // Wo transpose
        const int bb = b - (8192 + 6144);
        const int n0 = (bb % 64) * 32, k0 = (bb / 64) * 32;
        const int xL = tid & 31, y = tid >> 5;
#pragma unroll
        for (int j = 0; j < 4; j++) {
            const int k = y + j * 8;
            t[k][xL] = __float2half_rn(Wo[(size_t)(k0 + k) * EMB + n0 + xL]);
        }
        __syncthreads();
#pragma unroll
        for (int j = 0; j < 4; j++) {
            const int n = y + j * 8;
            wot[(size_t)(n0 + n) * EMB + k0 + xL] = t[xL][n];
        }
        return;
    }
    {                                                // rope table
        const int idx = (b - (8192 + 6144 + 4096)) * 256 + tid;
        const int s = idx >> 6, i = idx & 63;
        const float freq = powf(10000.0f, -(float)i / 64.0f);
        const float ang  = (float)pos[s] * freq;
        float sv, cv;
        sincosf(ang, &sv, &cv);
        g_rcos[s * 64 + i] = cv;
        g_rsin[s * 64 + i] = sv;
    }
}

// ---------------- fp16 MMA GEMM: 128 thr, 4 warps of 64x64, 2-stage --------
#define GSTG_H   (128 * 72)
#define GEMM_SMEM_BYTES (4 * GSTG_H * 2)        // 73728 B

#define HGEMM_BODY(C_STORE)                                                     \
    extern __shared__ __half sh[];                                             \
    const u32 shb = smem_u32(sh);                                              \
    const int tid  = threadIdx.x;                                              \
    const int lane = tid & 31;                                                 \
    const int wid  = tid >> 5;          /* 0..3 */                             \
    const int wm   = wid >> 1;          /* 0..1 */                             \
    const int wn   = wid & 1;           /* 0..1 */                             \
    const int g    = lane >> 2;                                                \
    const int t    = lane & 3;                                                 \
    const int row0 = blockIdx.y * 128;                                         \
    const int col0 = blockIdx.x * 128;                                         \
    const int l_r  = tid >> 3;          /* 0..15 */                            \
    const int l_c8 = (tid & 7) * 8;                                            \
    const u32 a_loff = ((u32)((((lane >> 3) & 1) * 8 + (lane & 7)) * 72)       \
                        + (u32)((lane >> 4) * 8)) * 2;                         \
    const u32 b_loff = ((u32)((((lane >> 4) & 1) * 8 + (lane & 7)) * 72)       \
                        + (u32)(((lane >> 3) & 1) * 8)) * 2;                   \
    float c[4][8][4];                                                          \
    _Pragma("unroll")                                                          \
    for (int i = 0; i < 4; i++)                                                \
        _Pragma("unroll")                                                      \
        for (int n = 0; n < 8; n++)                                            \
            _Pragma("unroll")                                                  \
            for (int r = 0; r < 4; r++) c[i][n][r] = 0.f;                      \
    const int NS = K >> 6;                                                     \
    auto issue = [&](int s) {                                                  \
        const int kb   = s << 6;                                               \
        const u32 base = shb + (u32)(s & 1) * (2 * GSTG_H * 2);                \
        const u32 ab   = base;                                                 \
        const u32 bb   = base + GSTG_H * 2;                                    \
        _Pragma("unroll")                                                      \
        for (int j = 0; j < 8; j++) {                                          \
            const int r = l_r + j * 16;                                        \
            cp16(ab + (u32)(r * 72 + l_c8) * 2,                                \
                 &A[(size_t)(row0 + r) * K + kb + l_c8]);                      \
            cp16(bb + (u32)(r * 72 + l_c8) * 2,                                \
                 &B[(size_t)(col0 + r) * K + kb + l_c8]);                      \
        }                                                                      \
        CP_COMMIT();                                                           \
    };                                                                         \
    issue(0);                                                                  \
    for (int s = 0; s < NS; s++) {                                             \
        if (s + 1 < NS) issue(s + 1);                                          \
        if (s + 1 < NS) { CP_WAIT(1); } else { CP_WAIT(0); }                   \
        __syncthreads();                                                       \
        const u32 asb = shb + (u32)(s & 1) * (2 * GSTG_H * 2) + a_loff;        \
        const u32 bsb = shb + (u32)(s & 1) * (2 * GSTG_H * 2) + GSTG_H * 2     \
                        + b_loff;                                              \
        _Pragma("unroll")                                                      \
        for (int kt = 0; kt < 4; kt++) {                                       \
            uint4 af[4];                                                       \
            _Pragma("unroll")                                                  \
            for (int mt = 0; mt < 4; mt++) {                                   \
                u32 aq[4];                                                     \
                ldsm4(aq, asb + (u32)(((wm * 64 + mt * 16) * 72                \
                                       + kt * 16) * 2));                       \
                af[mt] = make_uint4(aq[0], aq[1], aq[2], aq[3]);               \
            }                                                                  \
            u32 bf[8][2];                                                      \
            _Pragma("unroll")                                                  \
            for (int pr = 0; pr < 4; pr++) {                                   \
                u32 bq[4];                                                     \
                ldsm4(bq, bsb + (u32)(((wn * 64 + pr * 16) * 72                \
                                       + kt * 16) * 2));                       \
                bf[2 * pr][0]     = bq[0]; bf[2 * pr][1]     = bq[1];          \
                bf[2 * pr + 1][0] = bq[2]; bf[2 * pr + 1][1] = bq[3];          \
            }                                                                  \
            _Pragma("unroll")                                                  \
            for (int mt = 0; mt < 4; mt++)                                     \
                _Pragma("unroll")                                              \
                for (int nt = 0; nt < 8; nt++)                                 \
                    mma_f16(c[mt][nt], af[mt], bf[nt][0], bf[nt][1]);          \
        }                                                                      \
        __syncthreads();                                                       \
    }                                                                          \
    _Pragma("unroll")                                                          \
    for (int mt = 0; mt < 4; mt++) {                                           \
        const int row = row0 + wm * 64 + mt * 16 + g;                          \
        _Pragma("unroll")                                                      \
        for (int nt = 0; nt < 8; nt++) {                                       \
            const int col = col0 + wn * 64 + nt * 8 + 2 * t;                   \
            C_STORE                                                            \
        }                                                                      \
    }

__global__ void __launch_bounds__(128, 2) hgemm(const __half* __restrict__ A,
                                                const __half* __restrict__ B,
                                                float* __restrict__ C,
                                                int M, int N, int K) {
    HGEMM_BODY(
        *(float2*)&C[(size_t)row * N + col] =
            make_float2(c[mt][nt][0], c[mt][nt][1]);
        *(float2*)&C[(size_t)(row + 8) * N + col] =
            make_float2(c[mt][nt][2], c[mt][nt][3]);
    )
}

__global__ void __launch_bounds__(128, 2) hgemm_h(const __half* __restrict__ A,
                                                  const __half* __restrict__ B,
                                                  __half* __restrict__ C,
                                                  int M, int N, int K) {
    HGEMM_BODY(
        *(u32*)&C[(size_t)row * N + col]       = f2h2(c[mt][nt][0], c[mt][nt][1]);
        *(u32*)&C[(size_t)(row + 8) * N + col] = f2h2(c[mt][nt][2], c[mt][nt][3]);
    )
}

// ---------------- RMSNorm + RoPE from half qkv -------------------------------
__global__ void __launch_bounds__(256) norm_rope_kernel(
    const __half* __restrict__ qkv,
    const float* __restrict__ qw, const float* __restrict__ kw,
    __half* __restrict__ qout,
    float*  __restrict__ kout,  float* __restrict__ vout,
    __half* __restrict__ khalf, __half* __restrict__ vhalf)
{
    const int s = blockIdx.x;
    const int w = threadIdx.x >> 5;
    const int l = threadIdx.x & 31;
    const int c = l * 4;
    const __half* row = qkv + (size_t)s * QKV_N;

#pragma unroll
    for (int uu = 0; uu < 3; uu++) {
        const int unit = w + uu * 8;
        if (unit >= 20) {
            const int kv = unit - 20;
            uint2 hv = *(const uint2*)&row[2560 + kv * HDIM + c];
            __half2 h0 = *(__half2*)&hv.x, h1 = *(__half2*)&hv.y;
            float2 a = __half22float2(h0), b2 = __half22float2(h1);
            *(float4*)&vout[((size_t)kv * SEQ + s) * HDIM + c] =
                make_float4(a.x, a.y, b2.x, b2.y);
            *(uint2*)&vhalf[((size_t)kv * SEQ + s) * HDIM + c] = hv;
            continue;
        }
        float4 v; const float* wptr;
        {
            const int off = (unit < 16) ? unit * HDIM + c
                                        : 2048 + (unit - 16) * HDIM + c;
            uint2 hv = *(const uint2*)&row[off];
            __half2 h0 = *(__half2*)&hv.x, h1 = *(__half2*)&hv.y;
            float2 a = __half22float2(h0), b2 = __half22float2(h1);
            v = make_float4(a.x, a.y, b2.x, b2.y);
            wptr = (unit < 16) ? qw : kw;
        }

        float sq = v.x * v.x + v.y * v.y + v.z * v.z + v.w * v.w;
#pragma unroll
        for (int off = 16; off > 0; off >>= 1)
            sq += __shfl_xor_sync(0xffffffffu, sq, off);
        const float inv = rsqrtf(sq * (1.0f / HDIM) + 1e-6f);
        const float4 wv = *(const float4*)&wptr[c];
        float xn[4] = {wv.x * v.x * inv, wv.y * v.y * inv,
                       wv.z * v.z * inv, wv.w * v.w * inv};
        float pr[4];
#pragma unroll
        for (int i = 0; i < 4; i++)
            pr[i] = __shfl_xor_sync(0xffffffffu, xn[i], 16);
        const float4 cs = *(const float4*)&g_rcos[s * 64 + (c & 63)];
        const float4 sn = *(const float4*)&g_rsin[s * 64 + (c & 63)];
        const float cc[4] = {cs.x, cs.y, cs.z, cs.w};
        const float ss[4] = {sn.x, sn.y, sn.z, sn.w};
        float o[4];
#pragma unroll
        for (int i = 0; i < 4; i++)
            o[i] = (l < 16) ? (xn[i] * cc[i] - pr[i] * ss[i])
                            : (xn[i] * cc[i] + pr[i] * ss[i]);
        if (unit < 16) {
            *(uint2*)&qout[((size_t)unit * SEQ + s) * HDIM + c] =
                make_uint2(f2h2(o[0] * QSCL, o[1] * QSCL),
                           f2h2(o[2] * QSCL, o[3] * QSCL));
        } else {
            const int kvh = unit - 16;
            *(float4*)&kout[((size_t)kvh * SEQ + s) * HDIM + c] =
                make_float4(o[0], o[1], o[2], o[3]);
            *(uint2*)&khalf[((size_t)kvh * SEQ + s) * HDIM + c] =
                make_uint2(f2h2(o[0], o[1]), f2h2(o[2], o[3]));
        }
    }
}

// ---------------- Flash attention: BM=128, BN=128, register-P FA2 ----------
#define FQ_LD 136
#define KS_LD 136
#define VS_LD 136
#define KS_TILE_H (128 * KS_LD)
#define VS_TILE_H (128 * VS_LD)
#define FLASH_SMEM_HALVES (128*FQ_LD + 2*KS_TILE_H + 2*VS_TILE_H)
#define FLASH_SMEM_BYTES  (FLASH_SMEM_HALVES * 2)

__global__ void __launch_bounds__(256, 1) flash_f16(
    const __half* __restrict__ Q,
    const __half* __restrict__ Kh,
    const __half* __restrict__ Vh,
    __half* __restrict__ ctx)
{
    extern __shared__ __half smh[];
    __half* Qs = smh;                          // [128][136]
    __half* Ks = Qs + 128 * FQ_LD;             // 2 x [128][136]
    __half* Vs = Ks + 2 * KS_TILE_H;           // 2 x [128][136]

    const u32 ksb0 = smem_u32(Ks);
    const u32 vsb0 = smem_u32(Vs);

    const int tid  = threadIdx.x;
    const int lane = tid & 31;
    const int w    = tid >> 5;
    const int g    = lane >> 2;
    const int t    = lane & 3;
    const int qt   = (gridDim.x - 1) - blockIdx.x;   // big tiles first
    const int head = blockIdx.y;
    const int kv   = head / GROUP;
    const int q0   = qt * 128;
    const int rw   = w * 16;

    const u32 k_off = ((u32)(((lane >> 4) & 1) * 8 + (lane & 7)) * KS_LD
                       + (u32)(((lane >> 3) & 1) * 8)) * 2;
    const u32 v_off = ((u32)(((lane >> 3) & 1) * 8 + (lane & 7)) * VS_LD
                       + (u32)((lane >> 4) * 8)) * 2;

    const __half* kg = Kh + (size_t)kv * SEQ * HDIM;
    const __half* vg = Vh + (size_t)kv * SEQ * HDIM;
    const int l_r  = tid >> 4;
    const int l_c8 = (tid & 15) * 8;

    const int njt = qt + 1;

    auto issue = [&](int jt) {
        const int k0 = jt * 128;
        const u32 kd = ksb0 + (u32)(jt & 1) * (KS_TILE_H * 2);
        const u32 vd = vsb0 + (u32)(jt & 1) * (VS_TILE_H * 2);
#pragma unroll
        for (int j = 0; j < 8; j++) {
            const int r = l_r + j * 16;
            cp16(kd + (u32)(r * KS_LD + l_c8) * 2,
                 kg + (size_t)(k0 + r) * HDIM + l_c8);
            cp16(vd + (u32)(r * VS_LD + l_c8) * 2,
                 vg + (size_t)(k0 + r) * HDIM + l_c8);
        }
        CP_COMMIT();
    };

    issue(0);
    if (njt > 1) issue(1);
    {
        const uint4* src = (const uint4*)(Q + ((size_t)head * SEQ + q0) * HDIM);
#pragma unroll
        for (int j = 0; j < 8; j++) {
            const int i = tid + j * 256;
            const int r = i >> 4, c8 = (i & 15) * 8;
            *(uint4*)&Qs[r * FQ_LD + c8] = src[r * 16 + (i & 15)];
        }
    }
    __syncthreads();

    uint4 af[8];
#pragma unroll
    for (int kt = 0; kt < 8; kt++) {
        af[kt].x = *(const u32*)&Qs[(rw + g)     * FQ_LD + kt * 16 + 2 * t];
        af[kt].y = *(const u32*)&Qs[(rw + g + 8) * FQ_LD + kt * 16 + 2 * t];
        af[kt].z = *(const u32*)&Qs[(rw + g)     * FQ_LD + kt * 16 + 2 * t + 8];
        af[kt].w = *(const u32*)&Qs[(rw + g + 8) * FQ_LD + kt * 16 + 2 * t + 8];
    }

    float o[16][4];
#pragma unroll
    for (int n = 0; n < 16; n++)
#pragma unroll
        for (int r = 0; r < 4; r++) o[n][r] = 0.f;
    float mA = -INFINITY, mB = -INFINITY, lA = 0.f, lB = 0.f;

    const int rowA = q0 + rw + g;
    const int rowB = rowA + 8;

    for (int jt = 0; jt < njt; jt++) {
        const int k0 = jt * 128;
        if (jt + 1 < njt) { CP_WAIT(1); } else { CP_WAIT(0); }
        __syncthreads();

        const u32 kfb = ksb0 + (u32)(jt & 1) * (KS_TILE_H * 2) + k_off;
        const u32 vfb = vsb0 + (u32)(jt & 1) * (VS_TILE_H * 2) + v_off;

        // ---- S = Q @ K^T  (scores already in log2 domain via QSCL) ----
        float s[16][4];
#pragma unroll
        for (int n = 0; n < 16; n++)
#pragma unroll
            for (int r = 0; r < 4; r++) s[n][r] = 0.f;
#pragma unroll
        for (int kt = 0; kt < 8; kt++) {
#pragma unroll
            for (int np = 0; np < 8; np++) {
                u32 bf[4];
                ldsm4(bf, kfb + (u32)(np * 16 * KS_LD + kt * 16) * 2);
                mma_f16(s[2 * np],     af[kt], bf[0], bf[1]);
                mma_f16(s[2 * np + 1], af[kt], bf[2], bf[3]);
            }
        }

        // ---- causal mask (diag tile only) ----
        if (jt == qt) {
#pragma unroll
            for (int nt = 0; nt < 16; nt++) {
                const int c0 = k0 + nt * 8 + 2 * t;
                const int c1 = c0 + 1;
                if (c0 > rowA) s[nt][0] = -1e30f;
                if (c1 > rowA) s[nt][1] = -1e30f;
                if (c0 > rowB) s[nt][2] = -1e30f;
                if (c1 > rowB) s[nt][3] = -1e30f;
            }
        }

        // ---- online softmax (base-2); P packed straight into A-fragments ----
        float mxA = -1e30f, mxB = -1e30f;
#pragma unroll
        for (int nt = 0; nt < 16; nt++) {
            mxA = fmaxf(mxA, fmaxf(s[nt][0], s[nt][1]));
            mxB = fmaxf(mxB, fmaxf(s[nt][2], s[nt][3]));
        }
        mxA = fmaxf(mxA, __shfl_xor_sync(0xffffffffu, mxA, 1));
        mxA = fmaxf(mxA, __shfl_xor_sync(0xffffffffu, mxA, 2));
        mxB = fmaxf(mxB, __shfl_xor_sync(0xffffffffu, mxB, 1));
        mxB = fmaxf(mxB, __shfl_xor_sync(0xffffffffu, mxB, 2));

        const float mnA = fmaxf(mA, mxA);
        const float mnB = fmaxf(mB, mxB);
        const float cA  = exp2f(mA - mnA);
        const float cB  = exp2f(mB - mnB);

        uint4 pf8[8];
        float sA = 0.f, sB = 0.f;
#pragma unroll
        for (int kt = 0; kt < 8; kt++) {
#pragma unroll
            for (int h = 0; h < 2; h++) {
                const int nt = 2 * kt + h;
                const float p0 = exp2f(s[nt][0] - mnA);
                const float p1 = exp2f(s[nt][1] - mnA);
                const float p2 = exp2f(s[nt][2] - mnB);
                const float p3 = exp2f(s[nt][3] - mnB);
                sA += p0 + p1;  sB += p2 + p3;
                if (h == 0) { pf8[kt].x = f2h2(p0, p1); pf8[kt].y = f2h2(p2, p3); }
                else        { pf8[kt].z = f2h2(p0, p1); pf8[kt].w = f2h2(p2, p3); }
            }
        }
        sA += __shfl_xor_sync(0xffffffffu, sA, 1);
        sA += __shfl_xor_sync(0xffffffffu, sA, 2);
        sB += __shfl_xor_sync(0xffffffffu, sB, 1);
        sB += __shfl_xor_sync(0xffffffffu, sB, 2);

        lA = lA * cA + sA;  lB = lB * cB + sB;
        mA = mnA;           mB = mnB;
#pragma unroll
        for (int nt = 0; nt < 16; nt++) {
            o[nt][0] *= cA;  o[nt][1] *= cA;
            o[nt][2] *= cB;  o[nt][3] *= cB;
        }

        // ---- O += P @ V (P from registers) ----
#pragma unroll
        for (int kt = 0; kt < 8; kt++) {
#pragma unroll
            for (int np = 0; np < 8; np++) {
                u32 bf[4];
                ldsm4t(bf, vfb + (u32)(kt * 16 * VS_LD + np * 16) * 2);
                mma_f16(o[2 * np],     pf8[kt], bf[0], bf[1]);
                mma_f16(o[2 * np + 1], pf8[kt], bf[2], bf[3]);
            }
        }
        __syncthreads();
        if (jt + 2 < njt) issue(jt + 2);
    }

    const float iA = 1.0f / lA;
    const float iB = 1.0f / lB;
#pragma unroll
    for (int nt = 0; nt < 16; nt++) {
        const int col = head * HDIM + nt * 8 + 2 * t;
        *(u32*)&ctx[(size_t)rowA * EMB + col] = f2h2(o[nt][0] * iA, o[nt][1] * iA);
        *(u32*)&ctx[(size_t)rowB * EMB + col] = f2h2(o[nt][2] * iB, o[nt][3] * iB);
    }
}

// ---------------- launch ----------------------------------------------------
extern "C" void kernel_launch(void* const* d_in, const int* in_sizes, int n_in,
                              void* d_out, int out_size) {
    const float* x   = (const float*)d_in[0];
    const int*   pos = (const int*)  d_in[1];
    // d_in[2] = attn_mask (pure causal) -- analytic
    const float* Wq  = (const float*)d_in[3];
    const float* Wk  = (const float*)d_in[4];
    const float* Wv  = (const float*)d_in[5];
    const float* Wo  = (const float*)d_in[6];
    const float* qw  = (const float*)d_in[7];
    const float* kw  = (const float*)d_in[8];

    float* out  = (float*)d_out;
    float* kout = out  + (size_t)SEQ * EMB;
    float* vout = kout + (size_t)NKV * SEQ * HDIM;

    __half *qkvh, *xh, *qh, *kh, *vh, *ctxh, *wqkvt, *wot;
    cudaGetSymbolAddress((void**)&qkvh,  g_qkvh);
    cudaGetSymbolAddress((void**)&xh,    g_xh);
    cudaGetSymbolAddress((void**)&qh,    g_qh);
    cudaGetSymbolAddress((void**)&kh,    g_kh);
    cudaGetSymbolAddress((void**)&vh,    g_vh);
    cudaGetSymbolAddress((void**)&ctxh,  g_ctxh);
    cudaGetSymbolAddress((void**)&wqkvt, g_wqkvt);
    cudaGetSymbolAddress((void**)&wot,   g_wot);

    cudaFuncSetAttribute(hgemm,
                         cudaFuncAttributeMaxDynamicSharedMemorySize, GEMM_SMEM_BYTES);
    cudaFuncSetAttribute(hgemm_h,
                         cudaFuncAttributeMaxDynamicSharedMemorySize, GEMM_SMEM_BYTES);
    cudaFuncSetAttribute(flash_f16,
                         cudaFuncAttributeMaxDynamicSharedMemorySize, FLASH_SMEM_BYTES);

    // 0) all prep in one launch
    prep_kernel<<<PREP_BLOCKS, 256>>>(x, Wq, Wk, Wv, Wo, pos, xh, wqkvt, wot);

    // 1) fused QKV projection (half output)
    hgemm_h<<<dim3(QKV_N / 128, SEQ / 128), 128, GEMM_SMEM_BYTES>>>(
        xh, wqkvt, qkvh, SEQ, QKV_N, EMB);

    // 2) rmsnorm + rope (Q pre-scaled for log2-domain softmax)
    norm_rope_kernel<<<SEQ, 256>>>(qkvh, qw, kw, qh, kout, vout, kh, vh);

    // 3) causal flash attention (register-P)
    flash_f16<<<dim3(SEQ / 128, NHEADS), 256, FLASH_SMEM_BYTES>>>(qh, kh, vh, ctxh);

    // 4) output projection
    hgemm<<<dim3(EMB / 128, SEQ / 128), 128, GEMM_SMEM_BYTES>>>(
        ctxh, wot, out, SEQ, EMB, EMB);
}

// round 16
// speedup vs baseline: 1.0215x; 1.0215x over previous
#include <cuda_runtime.h>
#include <cuda_fp16.h>
#include <math.h>
#include <stdint.h>

// Problem constants
#define SEQ      4096
#define EMB      2048
#define NHEADS   16
#define NKV      4
#define HDIM     128
#define GROUP    (NHEADS / NKV)
#define QKV_N    3072            // 2048 Q + 512 K + 512 V

typedef unsigned long long u64;
typedef unsigned int u32;

// softmax scale folded into Q: 1/sqrt(128) * log2(e)
#define QSCL 0.12753102694420f

// ---------------- scratch (device globals; no allocation allowed) ----------
__device__ __half g_qkvh[SEQ * QKV_N];            // fused projection (half)
__device__ __half g_xh  [SEQ * EMB];
__device__ __half g_qh  [NHEADS * SEQ * HDIM];
__device__ __half g_kh  [NKV * SEQ * HDIM];
__device__ __half g_vh  [NKV * SEQ * HDIM];
__device__ __half g_ctxh[SEQ * NHEADS * HDIM];
__device__ float  g_rcos[SEQ * 64];
__device__ float  g_rsin[SEQ * 64];
__device__ __half g_wqkvt[QKV_N * EMB];           // [3072][2048]
__device__ __half g_wot  [EMB * EMB];

// ---------------- helpers ----------------------------------------------------
__device__ __forceinline__ u32 f2h2(float lo, float hi) {
    __half2 h = __floats2half2_rn(lo, hi);
    return *reinterpret_cast<u32*>(&h);
}
__device__ __forceinline__ void mma_f16(float c[4], uint4 a, u32 b0, u32 b1) {
    asm("mma.sync.aligned.m16n8k16.row.col.f32.f16.f16.f32 "
        "{%0,%1,%2,%3},{%4,%5,%6,%7},{%8,%9},{%0,%1,%2,%3};"
        : "+f"(c[0]), "+f"(c[1]), "+f"(c[2]), "+f"(c[3])
        : "r"(a.x), "r"(a.y), "r"(a.z), "r"(a.w), "r"(b0), "r"(b1));
}
__device__ __forceinline__ u32 smem_u32(const void* p) {
    u32 a;
    asm("{ .reg .u64 t; cvta.to.shared.u64 t, %1; cvt.u32.u64 %0, t; }"
        : "=r"(a) : "l"(p));
    return a;
}
__device__ __forceinline__ void cp16(u32 saddr, const void* gptr) {
    asm volatile("cp.async.cg.shared.global [%0], [%1], 16;"
                 :: "r"(saddr), "l"(gptr) : "memory");
}
#define CP_COMMIT() asm volatile("cp.async.commit_group;" ::: "memory")
#define CP_WAIT(n)  asm volatile("cp.async.wait_group %0;" :: "n"(n) : "memory")

__device__ __forceinline__ void ldsm4(u32 r[4], u32 saddr) {
    asm volatile("ldmatrix.sync.aligned.m8n8.x4.shared.b16 {%0,%1,%2,%3}, [%4];"
                 : "=r"(r[0]), "=r"(r[1]), "=r"(r[2]), "=r"(r[3]) : "r"(saddr));
}
__device__ __forceinline__ void ldsm4t(u32 r[4], u32 saddr) {
    asm volatile("ldmatrix.sync.aligned.m8n8.x4.trans.shared.b16 {%0,%1,%2,%3}, [%4];"
                 : "=r"(r[0]), "=r"(r[1]), "=r"(r[2]), "=r"(r[3]) : "r"(saddr));
}

// ---------------- merged prep kernel ----------------------------------------
#define PREP_BLOCKS (8192 + 6144 + 4096 + 1024)

__global__ void __launch_bounds__(256) prep_kernel(
    const float* __restrict__ x,
    const float* __restrict__ Wq, const float* __restrict__ Wk,
    const float* __restrict__ Wv, const float* __restrict__ Wo,
    const int* __restrict__ pos,
    __half* __restrict__ xh, __half* __restrict__ wqkvt,
    __half* __restrict__ wot)
{
    __shared__ __half t[32][33];
    const int b   = blockIdx.x;
    const int tid = threadIdx.x;

    if (b < 8192) {                                  // x -> half
        const int i = b * 256 + tid;
        float4 v = ((const float4*)x)[i];
        ((uint2*)xh)[i] = make_uint2(f2h2(v.x, v.y), f2h2(v.z, v.w));
        return;
    }
    if (b < 8192 + 6144) {                           // QKV transpose
        const int bb = b - 8192;
        const int n0 = (bb % 96) * 32, k0 = (bb / 96) * 32;
        const int xL = tid & 31, y = tid >> 5;
        const float* src; int N, nl;
        if      (n0 < 2048) { src = Wq; N = 2048; nl = n0; }
        else if (n0 < 2560) { src = Wk; N = 512;  nl = n0 - 2048; }
        else                { src = Wv; N = 512;  nl = n0 - 2560; }
#pragma unroll
        for (int j = 0; j < 4; j++) {
            const int k = y + j * 8;
            t[k][xL] = __float2half_rn(src[(size_t)(k0 + k) * N + nl + xL]);
        }
        __syncthreads();
#pragma unroll
        for (int j = 0; j < 4; j++) {
            const int n = y + j * 8;
            wqkvt[(size_t)(n0 + n) * EMB + k0 + xL] = t[xL][n];
        }
        return;
    }
    if (b < 8192 + 6144 + 4096) {                    // Wo transpose
        const int bb = b - (8192 + 6144);
        const int n0 = (bb % 64) * 32, k0 = (bb / 64) * 32;
        const int xL = tid & 31, y = tid >> 5;
#pragma unroll
        for (int j = 0; j < 4; j++) {
            const int k = y + j * 8;
            t[k][xL] = __float2half_rn(Wo[(size_t)(k0 + k) * EMB + n0 + xL]);
        }
        __syncthreads();
#pragma unroll
        for (int j = 0; j < 4; j++) {
            const int n = y + j * 8;
            wot[(size_t)(n0 + n) * EMB + k0 + xL] = t[xL][n];
        }
        return;
    }
    {                                                // rope table
        const int idx = (b - (8192 + 6144 + 4096)) * 256 + tid;
        const int s = idx >> 6, i = idx & 63;
        const float freq = powf(10000.0f, -(float)i / 64.0f);
        const float ang  = (float)pos[s] * freq;
        float sv, cv;
        sincosf(ang, &sv, &cv);
        g_rcos[s * 64 + i] = cv;
        g_rsin[s * 64 + i] = sv;
    }
}

// ---------------- fp16 MMA GEMM core: 3-stage cp.async, 1 sync/chunk --------
// (round-14 configuration: 256 threads, 8 warps 2x4, warp tile 64x32)
#define GSTG_H   (128 * 72)
#define GEMM_SMEM_BYTES (3 * 2 * GSTG_H * 2)    // 110592 B

#define HGEMM_BODY(C_STORE)                                                     \
    extern __shared__ __half sh[];                                             \
    const u32 shb = smem_u32(sh);                                              \
    const int tid  = threadIdx.x;                                              \
    const int lane = tid & 31;                                                 \
    const int wid  = tid >> 5;                                                 \
    const int wm   = wid >> 2;                                                 \
    const int wn   = wid & 3;                                                  \
    const int g    = lane >> 2;                                                \
    const int t    = lane & 3;                                                 \
    const int row0 = blockIdx.y * 128;                                         \
    const int col0 = blockIdx.x * 128;                                         \
    const int l_r  = tid >> 3;                                                 \
    const int l_c8 = (tid & 7) * 8;                                            \
    const u32 a_loff = ((u32)((((lane >> 3) & 1) * 8 + (lane & 7)) * 72)       \
                        + (u32)((lane >> 4) * 8)) * 2;                         \
    const u32 b_loff = ((u32)((((lane >> 4) & 1) * 8 + (lane & 7)) * 72)       \
                        + (u32)(((lane >> 3) & 1) * 8)) * 2;                   \
    float c[4][4][4];                                                          \
    _Pragma("unroll")                                                          \
    for (int i = 0; i < 4; i++)                                                \
        _Pragma("unroll")                                                      \
        for (int n = 0; n < 4; n++)                                            \
            _Pragma("unroll")                                                  \
            for (int r = 0; r < 4; r++) c[i][n][r] = 0.f;                      \
    const int NS = K >> 6;                                                     \
    auto issue = [&](int s, int bufi) {                                        \
        const int kb   = s << 6;                                               \
        const u32 base = shb + (u32)bufi * (2 * GSTG_H * 2);                   \
        const u32 ab   = base;                                                 \
        const u32 bb   = base + GSTG_H * 2;                                    \
        _Pragma("unroll")                                                      \
        for (int j = 0; j < 4; j++) {                                          \
            const int r = l_r + j * 32;                                        \
            cp16(ab + (u32)(r * 72 + l_c8) * 2,                                \
                 &A[(size_t)(row0 + r) * K + kb + l_c8]);                      \
            cp16(bb + (u32)(r * 72 + l_c8) * 2,                                \
                 &B[(size_t)(col0 + r) * K + kb + l_c8]);                      \
        }                                                                      \
        CP_COMMIT();                                                           \
    };                                                                         \
    issue(0, 0);                                                               \
    if (NS > 1) issue(1, 1);                                                   \
    int buf = 0;                                                               \
    for (int s = 0; s < NS; s++) {                                             \
        if (s + 1 < NS) { CP_WAIT(1); } else { CP_WAIT(0); }                   \
        __syncthreads();                                                       \
        if (s + 2 < NS) {                                                      \
            int ib = buf + 2; if (ib >= 3) ib -= 3;                            \
            issue(s + 2, ib);                                                  \
        }                                                                      \
        const u32 asb = shb + (u32)buf * (2 * GSTG_H * 2) + a_loff;            \
        const u32 bsb = shb + (u32)buf * (2 * GSTG_H * 2) + GSTG_H * 2         \
                        + b_loff;                                              \
        _Pragma("unroll")                                                      \
        for (int kt = 0; kt < 4; kt++) {                                       \
            uint4 af[4];                                                       \
            _Pragma("unroll")                                                  \
            for (int mt = 0; mt < 4; mt++) {                                   \
                u32 aq[4];                                                     \
                ldsm4(aq, asb + (u32)(((wm * 64 + mt * 16) * 72                \
                                       + kt * 16) * 2));                       \
                af[mt] = make_uint4(aq[0], aq[1], aq[2], aq[3]);               \
            }                                                                  \
            u32 bf[4][2];                                                      \
            _Pragma("unroll")                                                  \
            for (int pr = 0; pr < 2; pr++) {                                   \
                u32 bq[4];                                                     \
                ldsm4(bq, bsb + (u32)(((wn * 32 + pr * 16) * 72                \
                                       + kt * 16) * 2));                       \
                bf[2 * pr][0]     = bq[0]; bf[2 * pr][1]     = bq[1];          \
                bf[2 * pr + 1][0] = bq[2]; bf[2 * pr + 1][1] = bq[3];          \
            }                                                                  \
            _Pragma("unroll")                                                  \
            for (int mt = 0; mt < 4; mt++)                                     \
                _Pragma("unroll")                                              \
                for (int nt = 0; nt < 4; nt++)                                 \
                    mma_f16(c[mt][nt], af[mt], bf[nt][0], bf[nt][1]);          \
        }                                                                      \
        buf = (buf == 2) ? 0 : buf + 1;                                        \
    }                                                                          \
    _Pragma("unroll")                                                          \
    for (int mt = 0; mt < 4; mt++) {                                           \
        const int row = row0 + wm * 64 + mt * 16 + g;                          \
        _Pragma("unroll")                                                      \
        for (int nt = 0; nt < 4; nt++) {                                       \
            const int col = col0 + wn * 32 + nt * 8 + 2 * t;                   \
            C_STORE                                                            \
        }                                                                      \
    }

__global__ void __launch_bounds__(256, 2) hgemm(const __half* __restrict__ A,
                                                const __half* __restrict__ B,
                                                float* __restrict__ C,
                                                int M, int N, int K) {
    HGEMM_BODY(
        *(float2*)&C[(size_t)row * N + col] =
            make_float2(c[mt][nt][0], c[mt][nt][1]);
        *(float2*)&C[(size_t)(row + 8) * N + col] =
            make_float2(c[mt][nt][2], c[mt][nt][3]);
    )
}

__global__ void __launch_bounds__(256, 2) hgemm_h(const __half* __restrict__ A,
                                                  const __half* __restrict__ B,
                                                  __half* __restrict__ C,
                                                  int M, int N, int K) {
    HGEMM_BODY(
        *(u32*)&C[(size_t)row * N + col]       = f2h2(c[mt][nt][0], c[mt][nt][1]);
        *(u32*)&C[(size_t)(row + 8) * N + col] = f2h2(c[mt][nt][2], c[mt][nt][3]);
    )
}

// ---------------- RMSNorm + RoPE from half qkv -------------------------------
__global__ void __launch_bounds__(256) norm_rope_kernel(
    const __half* __restrict__ qkv,
    const float* __restrict__ qw, const float* __restrict__ kw,
    __half* __restrict__ qout,
    float*  __restrict__ kout,  float* __restrict__ vout,
    __half* __restrict__ khalf, __half* __restrict__ vhalf)
{
    const int s = blockIdx.x;
    const int w = threadIdx.x >> 5;
    const int l = threadIdx.x & 31;
    const int c = l * 4;
    const __half* row = qkv + (size_t)s * QKV_N;

#pragma unroll
    for (int uu = 0; uu < 3; uu++) {
        const int unit = w + uu * 8;
        if (unit >= 20) {
            const int kv = unit - 20;
            uint2 hv = *(const uint2*)&row[2560 + kv * HDIM + c];
            __half2 h0 = *(__half2*)&hv.x, h1 = *(__half2*)&hv.y;
            float2 a = __half22float2(h0), b2 = __half22float2(h1);
            *(float4*)&vout[((size_t)kv * SEQ + s) * HDIM + c] =
                make_float4(a.x, a.y, b2.x, b2.y);
            *(uint2*)&vhalf[((size_t)kv * SEQ + s) * HDIM + c] = hv;
            continue;
        }
        float4 v; const float* wptr;
        {
            const int off = (unit < 16) ? unit * HDIM + c
                                        : 2048 + (unit - 16) * HDIM + c;
            uint2 hv = *(const uint2*)&row[off];
            __half2 h0 = *(__half2*)&hv.x, h1 = *(__half2*)&hv.y;
            float2 a = __half22float2(h0), b2 = __half22float2(h1);
            v = make_float4(a.x, a.y, b2.x, b2.y);
            wptr = (unit < 16) ? qw : kw;
        }

        float sq = v.x * v.x + v.y * v.y + v.z * v.z + v.w * v.w;
#pragma unroll
        for (int off = 16; off > 0; off >>= 1)
            sq += __shfl_xor_sync(0xffffffffu, sq, off);
        const float inv = rsqrtf(sq * (1.0f / HDIM) + 1e-6f);
        const float4 wv = *(const float4*)&wptr[c];
        float xn[4] = {wv.x * v.x * inv, wv.y * v.y * inv,
                       wv.z * v.z * inv, wv.w * v.w * inv};
        float pr[4];
#pragma unroll
        for (int i = 0; i < 4; i++)
            pr[i] = __shfl_xor_sync(0xffffffffu, xn[i], 16);
        const float4 cs = *(const float4*)&g_rcos[s * 64 + (c & 63)];
        const float4 sn = *(const float4*)&g_rsin[s * 64 + (c & 63)];
        const float cc[4] = {cs.x, cs.y, cs.z, cs.w};
        const float ss[4] = {sn.x, sn.y, sn.z, sn.w};
        float o[4];
#pragma unroll
        for (int i = 0; i < 4; i++)
            o[i] = (l < 16) ? (xn[i] * cc[i] - pr[i] * ss[i])
                            : (xn[i] * cc[i] + pr[i] * ss[i]);
        if (unit < 16) {
            *(uint2*)&qout[((size_t)unit * SEQ + s) * HDIM + c] =
                make_uint2(f2h2(o[0] * QSCL, o[1] * QSCL),
                           f2h2(o[2] * QSCL, o[3] * QSCL));
        } else {
            const int kvh = unit - 16;
            *(float4*)&kout[((size_t)kvh * SEQ + s) * HDIM + c] =
                make_float4(o[0], o[1], o[2], o[3]);
            *(uint2*)&khalf[((size_t)kvh * SEQ + s) * HDIM + c] =
                make_uint2(f2h2(o[0], o[1]), f2h2(o[2], o[3]));
        }
    }
}

// ---------------- Flash attention: BM=128, BN=128, register-P, paired ldsm -
#define FQ_LD 136
#define KS_LD 136
#define VS_LD 136
#define KS_TILE_H (128 * KS_LD)
#define VS_TILE_H (128 * VS_LD)
#define FLASH_SMEM_HALVES (128*FQ_LD + 2*KS_TILE_H + 2*VS_TILE_H)
#define FLASH_SMEM_BYTES  (FLASH_SMEM_HALVES * 2)

__global__ void __launch_bounds__(256, 1) flash_f16(
    const __half* __restrict__ Q,
    const __half* __restrict__ Kh,
    const __half* __restrict__ Vh,
    __half* __restrict__ ctx)
{
    extern __shared__ __half smh[];
    __half* Qs = smh;                          // [128][136]
    __half* Ks = Qs + 128 * FQ_LD;             // 2 x [128][136]
    __half* Vs = Ks + 2 * KS_TILE_H;           // 2 x [128][136]

    const u32 ksb0 = smem_u32(Ks);
    const u32 vsb0 = smem_u32(Vs);

    const int tid  = threadIdx.x;
    const int lane = tid & 31;
    const int w    = tid >> 5;
    const int g    = lane >> 2;
    const int t    = lane & 3;
    const int qt   = (gridDim.x - 1) - blockIdx.x;   // big tiles first
    const int head = blockIdx.y;
    const int kv   = head / GROUP;
    const int q0   = qt * 128;
    const int rw   = w * 16;

    const u32 k_off = ((u32)(((lane >> 4) & 1) * 8 + (lane & 7)) * KS_LD
                       + (u32)(((lane >> 3) & 1) * 8)) * 2;
    const u32 v_off = ((u32)(((lane >> 3) & 1) * 8 + (lane & 7)) * VS_LD
                       + (u32)((lane >> 4) * 8)) * 2;

    const __half* kg = Kh + (size_t)kv * SEQ * HDIM;
    const __half* vg = Vh + (size_t)kv * SEQ * HDIM;
    const int l_r  = tid >> 4;
    const int l_c8 = (tid & 15) * 8;

    const int njt = qt + 1;

    auto issue = [&](int jt) {
        const int k0 = jt * 128;
        const u32 kd = ksb0 + (u32)(jt & 1) * (KS_TILE_H * 2);
        const u32 vd = vsb0 + (u32)(jt & 1) * (VS_TILE_H * 2);
#pragma unroll
        for (int j = 0; j < 8; j++) {
            const int r = l_r + j * 16;
            cp16(kd + (u32)(r * KS_LD + l_c8) * 2,
                 kg + (size_t)(k0 + r) * HDIM + l_c8);
            cp16(vd + (u32)(r * VS_LD + l_c8) * 2,
                 vg + (size_t)(k0 + r) * HDIM + l_c8);
        }
        CP_COMMIT();
    };

    issue(0);
    if (njt > 1) issue(1);
    {
        const uint4* src = (const uint4*)(Q + ((size_t)head * SEQ + q0) * HDIM);
#pragma unroll
        for (int j = 0; j < 8; j++) {
            const int i = tid + j * 256;
            const int r = i >> 4, c8 = (i & 15) * 8;
            *(uint4*)&Qs[r * FQ_LD + c8] = src[r * 16 + (i & 15)];
        }
    }
    __syncthreads();

    uint4 af[8];
#pragma unroll
    for (int kt = 0; kt < 8; kt++) {
        af[kt].x = *(const u32*)&Qs[(rw + g)     * FQ_LD + kt * 16 + 2 * t];
        af[kt].y = *(const u32*)&Qs[(rw + g + 8) * FQ_LD + kt * 16 + 2 * t];
        af[kt].z = *(const u32*)&Qs[(rw + g)     * FQ_LD + kt * 16 + 2 * t + 8];
        af[kt].w = *(const u32*)&Qs[(rw + g + 8) * FQ_LD + kt * 16 + 2 * t + 8];
    }

    float o[16][4];
#pragma unroll
    for (int n = 0; n < 16; n++)
#pragma unroll
        for (int r = 0; r < 4; r++) o[n][r] = 0.f;
    float mA = -INFINITY, mB = -INFINITY, lA = 0.f, lB = 0.f;

    const int rowA = q0 + rw + g;
    const int rowB = rowA + 8;

    for (int jt = 0; jt < njt; jt++) {
        const int k0 = jt * 128;
        if (jt + 1 < njt) { CP_WAIT(1); } else { CP_WAIT(0); }
        __syncthreads();

        const u32 kfb = ksb0 + (u32)(jt & 1) * (KS_TILE_H * 2) + k_off;
        const u32 vfb = vsb0 + (u32)(jt & 1) * (VS_TILE_H * 2) + v_off;

        // ---- S = Q @ K^T  (paired ldsm for MLP) ----
        float s[16][4];
#pragma unroll
        for (int n = 0; n < 16; n++)
#pragma unroll
            for (int r = 0; r < 4; r++) s[n][r] = 0.f;
#pragma unroll
        for (int kt = 0; kt < 8; kt++) {
#pragma unroll
            for (int np = 0; np < 8; np += 2) {
                u32 bfa[4], bfb[4];
                ldsm4(bfa, kfb + (u32)(np       * 16 * KS_LD + kt * 16) * 2);
                ldsm4(bfb, kfb + (u32)((np + 1) * 16 * KS_LD + kt * 16) * 2);
                mma_f16(s[2 * np],     af[kt], bfa[0], bfa[1]);
                mma_f16(s[2 * np + 1], af[kt], bfa[2], bfa[3]);
                mma_f16(s[2 * np + 2], af[kt], bfb[0], bfb[1]);
                mma_f16(s[2 * np + 3], af[kt], bfb[2], bfb[3]);
            }
        }

        // ---- causal mask (diag tile only) ----
        if (jt == qt) {
#pragma unroll
            for (int nt = 0; nt < 16; nt++) {
                const int c0 = k0 + nt * 8 + 2 * t;
                const int c1 = c0 + 1;
                if (c0 > rowA) s[nt][0] = -1e30f;
                if (c1 > rowA) s[nt][1] = -1e30f;
                if (c0 > rowB) s[nt][2] = -1e30f;
                if (c1 > rowB) s[nt][3] = -1e30f;
            }
        }

        // ---- online softmax (base-2); P packed straight into A-fragments ----
        float mxA = -1e30f, mxB = -1e30f;
#pragma unroll
        for (int nt = 0; nt < 16; nt++) {
            mxA = fmaxf(mxA, fmaxf(s[nt][0], s[nt][1]));
            mxB = fmaxf(mxB, fmaxf(s[nt][2], s[nt][3]));
        }
        mxA = fmaxf(mxA, __shfl_xor_sync(0xffffffffu, mxA, 1));
        mxA = fmaxf(mxA, __shfl_xor_sync(0xffffffffu, mxA, 2));
        mxB = fmaxf(mxB, __shfl_xor_sync(0xffffffffu, mxB, 1));
        mxB = fmaxf(mxB, __shfl_xor_sync(0xffffffffu, mxB, 2));

        const float mnA = fmaxf(mA, mxA);
        const float mnB = fmaxf(mB, mxB);
        const float cA  = exp2f(mA - mnA);
        const float cB  = exp2f(mB - mnB);

        uint4 pf8[8];
        float sA = 0.f, sB = 0.f;
#pragma unroll
        for (int kt = 0; kt < 8; kt++) {
#pragma unroll
            for (int h = 0; h < 2; h++) {
                const int nt = 2 * kt + h;
                const float p0 = exp2f(s[nt][0] - mnA);
                const float p1 = exp2f(s[nt][1] - mnA);
                const float p2 = exp2f(s[nt][2] - mnB);
                const float p3 = exp2f(s[nt][3] - mnB);
                sA += p0 + p1;  sB += p2 + p3;
                if (h == 0) { pf8[kt].x = f2h2(p0, p1); pf8[kt].y = f2h2(p2, p3); }
                else        { pf8[kt].z = f2h2(p0, p1); pf8[kt].w = f2h2(p2, p3); }
            }
        }
        sA += __shfl_xor_sync(0xffffffffu, sA, 1);
        sA += __shfl_xor_sync(0xffffffffu, sA, 2);
        sB += __shfl_xor_sync(0xffffffffu, sB, 1);
        sB += __shfl_xor_sync(0xffffffffu, sB, 2);

        lA = lA * cA + sA;  lB = lB * cB + sB;
        mA = mnA;           mB = mnB;
#pragma unroll
        for (int nt = 0; nt < 16; nt++) {
            o[nt][0] *= cA;  o[nt][1] *= cA;
            o[nt][2] *= cB;  o[nt][3] *= cB;
        }

        // ---- O += P @ V (P from registers; paired ldsm) ----
#pragma unroll
        for (int kt = 0; kt < 8; kt++) {
#pragma unroll
            for (int np = 0; np < 8; np += 2) {
                u32 bfa[4], bfb[4];
                ldsm4t(bfa, vfb + (u32)(kt * 16 * VS_LD + np       * 16) * 2);
                ldsm4t(bfb, vfb + (u32)(kt * 16 * VS_LD + (np + 1) * 16) * 2);
                mma_f16(o[2 * np],     pf8[kt], bfa[0], bfa[1]);
                mma_f16(o[2 * np + 1], pf8[kt], bfa[2], bfa[3]);
                mma_f16(o[2 * np + 2], pf8[kt], bfb[0], bfb[1]);
                mma_f16(o[2 * np + 3], pf8[kt], bfb[2], bfb[3]);
            }
        }
        __syncthreads();
        if (jt + 2 < njt) issue(jt + 2);
    }

    const float iA = 1.0f / lA;
    const float iB = 1.0f / lB;
#pragma unroll
    for (int nt = 0; nt < 16; nt++) {
        const int col = head * HDIM + nt * 8 + 2 * t;
        *(u32*)&ctx[(size_t)rowA * EMB + col] = f2h2(o[nt][0] * iA, o[nt][1] * iA);
        *(u32*)&ctx[(size_t)rowB * EMB + col] = f2h2(o[nt][2] * iB, o[nt][3] * iB);
    }
}

// ---------------- launch ----------------------------------------------------
extern "C" void kernel_launch(void* const* d_in, const int* in_sizes, int n_in,
                              void* d_out, int out_size) {
    const float* x   = (const float*)d_in[0];
    const int*   pos = (const int*)  d_in[1];
    // d_in[2] = attn_mask (pure causal) -- analytic
    const float* Wq  = (const float*)d_in[3];
    const float* Wk  = (const float*)d_in[4];
    const float* Wv  = (const float*)d_in[5];
    const float* Wo  = (const float*)d_in[6];
    const float* qw  = (const float*)d_in[7];
    const float* kw  = (const float*)d_in[8];

    float* out  = (float*)d_out;
    float* kout = out  + (size_t)SEQ * EMB;
    float* vout = kout + (size_t)NKV * SEQ * HDIM;

    __half *qkvh, *xh, *qh, *kh, *vh, *ctxh, *wqkvt, *wot;
    cudaGetSymbolAddress((void**)&qkvh,  g_qkvh);
    cudaGetSymbolAddress((void**)&xh,    g_xh);
    cudaGetSymbolAddress((void**)&qh,    g_qh);
    cudaGetSymbolAddress((void**)&kh,    g_kh);
    cudaGetSymbolAddress((void**)&vh,    g_vh);
    cudaGetSymbolAddress((void**)&ctxh,  g_ctxh);
    cudaGetSymbolAddress((void**)&wqkvt, g_wqkvt);
    cudaGetSymbolAddress((void**)&wot,   g_wot);

    cudaFuncSetAttribute(hgemm,
                         cudaFuncAttributeMaxDynamicSharedMemorySize, GEMM_SMEM_BYTES);
    cudaFuncSetAttribute(hgemm_h,
                         cudaFuncAttributeMaxDynamicSharedMemorySize, GEMM_SMEM_BYTES);
    cudaFuncSetAttribute(flash_f16,
                         cudaFuncAttributeMaxDynamicSharedMemorySize, FLASH_SMEM_BYTES);

    // 0) all prep in one launch
    prep_kernel<<<PREP_BLOCKS, 256>>>(x, Wq, Wk, Wv, Wo, pos, xh, wqkvt, wot);

    // 1) fused QKV projection (half output)
    hgemm_h<<<dim3(QKV_N / 128, SEQ / 128), 256, GEMM_SMEM_BYTES>>>(
        xh, wqkvt, qkvh, SEQ, QKV_N, EMB);

    // 2) rmsnorm + rope (Q pre-scaled for log2-domain softmax)
    norm_rope_kernel<<<SEQ, 256>>>(qkvh, qw, kw, qh, kout, vout, kh, vh);

    // 3) causal flash attention (register-P, paired ldsm)
    flash_f16<<<dim3(SEQ / 128, NHEADS), 256, FLASH_SMEM_BYTES>>>(qh, kh, vh, ctxh);

    // 4) output projection
    hgemm<<<dim3(EMB / 128, SEQ / 128), 256, GEMM_SMEM_BYTES>>>(
        ctxh, wot, out, SEQ, EMB, EMB);
}

// round 17
// speedup vs baseline: 1.0254x; 1.0038x over previous
#include <cuda_runtime.h>
#include <cuda_fp16.h>
#include <math.h>
#include <stdint.h>

// Problem constants
#define SEQ      4096
#define EMB      2048
#define NHEADS   16
#define NKV      4
#define HDIM     128
#define GROUP    (NHEADS / NKV)
#define QKV_N    3072            // 2048 Q + 512 K + 512 V

typedef unsigned long long u64;
typedef unsigned int u32;

// softmax scale folded into Q: 1/sqrt(128) * log2(e)
#define QSCL 0.12753102694420f

// ---------------- scratch (device globals; no allocation allowed) ----------
__device__ __half g_qkvh[SEQ * QKV_N];            // fused projection (half)
__device__ __half g_xh  [SEQ * EMB];
__device__ __half g_qh  [NHEADS * SEQ * HDIM];
__device__ __half g_kh  [NKV * SEQ * HDIM];
__device__ __half g_vh  [NKV * SEQ * HDIM];
__device__ __half g_ctxh[SEQ * NHEADS * HDIM];
__device__ float  g_rcos[SEQ * 64];
__device__ float  g_rsin[SEQ * 64];
__device__ __half g_wqkvt[QKV_N * EMB];           // [3072][2048]
__device__ __half g_wot  [EMB * EMB];

// ---------------- helpers ----------------------------------------------------
__device__ __forceinline__ u32 f2h2(float lo, float hi) {
    __half2 h = __floats2half2_rn(lo, hi);
    return *reinterpret_cast<u32*>(&h);
}
__device__ __forceinline__ void mma_f16(float c[4], uint4 a, u32 b0, u32 b1) {
    asm("mma.sync.aligned.m16n8k16.row.col.f32.f16.f16.f32 "
        "{%0,%1,%2,%3},{%4,%5,%6,%7},{%8,%9},{%0,%1,%2,%3};"
        : "+f"(c[0]), "+f"(c[1]), "+f"(c[2]), "+f"(c[3])
        : "r"(a.x), "r"(a.y), "r"(a.z), "r"(a.w), "r"(b0), "r"(b1));
}
__device__ __forceinline__ u32 smem_u32(const void* p) {
    u32 a;
    asm("{ .reg .u64 t; cvta.to.shared.u64 t, %1; cvt.u32.u64 %0, t; }"
        : "=r"(a) : "l"(p));
    return a;
}
__device__ __forceinline__ void cp16(u32 saddr, const void* gptr) {
    asm volatile("cp.async.cg.shared.global [%0], [%1], 16;"
                 :: "r"(saddr), "l"(gptr) : "memory");
}
#define CP_COMMIT() asm volatile("cp.async.commit_group;" ::: "memory")
#define CP_WAIT(n)  asm volatile("cp.async.wait_group %0;" :: "n"(n) : "memory")

__device__ __forceinline__ void ldsm4(u32 r[4], u32 saddr) {
    asm volatile("ldmatrix.sync.aligned.m8n8.x4.shared.b16 {%0,%1,%2,%3}, [%4];"
                 : "=r"(r[0]), "=r"(r[1]), "=r"(r[2]), "=r"(r[3]) : "r"(saddr));
}
__device__ __forceinline__ void ldsm4t(u32 r[4], u32 saddr) {
    asm volatile("ldmatrix.sync.aligned.m8n8.x4.trans.shared.b16 {%0,%1,%2,%3}, [%4];"
                 : "=r"(r[0]), "=r"(r[1]), "=r"(r[2]), "=r"(r[3]) : "r"(saddr));
}

// ---------------- merged prep kernel ----------------------------------------
#define PREP_BLOCKS (8192 + 6144 + 4096 + 1024)

__global__ void __launch_bounds__(256) prep_kernel(
    const float* __restrict__ x,
    const float* __restrict__ Wq, const float* __restrict__ Wk,
    const float* __restrict__ Wv, const float* __restrict__ Wo,
    const int* __restrict__ pos,
    __half* __restrict__ xh, __half* __restrict__ wqkvt,
    __half* __restrict__ wot)
{
    __shared__ __half t[32][33];
    const int b   = blockIdx.x;
    const int tid = threadIdx.x;

    if (b < 8192) {                                  // x -> half
        const int i = b * 256 + tid;
        float4 v = ((const float4*)x)[i];
        ((uint2*)xh)[i] = make_uint2(f2h2(v.x, v.y), f2h2(v.z, v.w));
        return;
    }
    if (b < 8192 + 6144) {                           // QKV transpose
        const int bb = b - 8192;
        const int n0 = (bb % 96) * 32, k0 = (bb / 96) * 32;
        const int xL = tid & 31, y = tid >> 5;
        const float* src; int N, nl;
        if      (n0 < 2048) { src = Wq; N = 2048; nl = n0; }
        else if (n0 < 2560) { src = Wk; N = 512;  nl = n0 - 2048; }
        else                { src = Wv; N = 512;  nl = n0 - 2560; }
#pragma unroll
        for (int j = 0; j < 4; j++) {
            const int k = y + j * 8;
            t[k][xL] = __float2half_rn(src[(size_t)(k0 + k) * N + nl + xL]);
        }
        __syncthreads();
#pragma unroll
        for (int j = 0; j < 4; j++) {
            const int n = y + j * 8;
            wqkvt[(size_t)(n0 + n) * EMB + k0 + xL] = t[xL][n];
        }
        return;
    }
    if (b < 8192 + 6144 + 4096) {                    // Wo transpose
        const int bb = b - (8192 + 6144);
        const int n0 = (bb % 64) * 32, k0 = (bb / 64) * 32;
        const int xL = tid & 31, y = tid >> 5;
#pragma unroll
        for (int j = 0; j < 4; j++) {
            const int k = y + j * 8;
            t[k][xL] = __float2half_rn(Wo[(size_t)(k0 + k) * EMB + n0 + xL]);
        }
        __syncthreads();
#pragma unroll
        for (int j = 0; j < 4; j++) {
            const int n = y + j * 8;
            wot[(size_t)(n0 + n) * EMB + k0 + xL] = t[xL][n];
        }
        return;
    }
    {                                                // rope table
        const int idx = (b - (8192 + 6144 + 4096)) * 256 + tid;
        const int s = idx >> 6, i = idx & 63;
        const float freq = powf(10000.0f, -(float)i / 64.0f);
        const float ang  = (float)pos[s] * freq;
        float sv, cv;
        sincosf(ang, &sv, &cv);
        g_rcos[s * 64 + i] = cv;
        g_rsin[s * 64 + i] = sv;
    }
}

// ---------------- fp16 MMA GEMM core: 3-stage cp.async, 1 sync/chunk --------
#define GSTG_H   (128 * 72)
#define GEMM_SMEM_BYTES (3 * 2 * GSTG_H * 2)    // 110592 B

#define HGEMM_BODY(C_STORE)                                                     \
    extern __shared__ __half sh[];                                             \
    const u32 shb = smem_u32(sh);                                              \
    const int tid  = threadIdx.x;                                              \
    const int lane = tid & 31;                                                 \
    const int wid  = tid >> 5;                                                 \
    const int wm   = wid >> 2;                                                 \
    const int wn   = wid & 3;                                                  \
    const int g    = lane >> 2;                                                \
    const int t    = lane & 3;                                                 \
    const int row0 = blockIdx.y * 128;                                         \
    const int col0 = blockIdx.x * 128;                                         \
    const int l_r  = tid >> 3;                                                 \
    const int l_c8 = (tid & 7) * 8;                                            \
    const u32 a_loff = ((u32)((((lane >> 3) & 1) * 8 + (lane & 7)) * 72)       \
                        + (u32)((lane >> 4) * 8)) * 2;                         \
    const u32 b_loff = ((u32)((((lane >> 4) & 1) * 8 + (lane & 7)) * 72)       \
                        + (u32)(((lane >> 3) & 1) * 8)) * 2;                   \
    float c[4][4][4];                                                          \
    _Pragma("unroll")                                                          \
    for (int i = 0; i < 4; i++)                                                \
        _Pragma("unroll")                                                      \
        for (int n = 0; n < 4; n++)                                            \
            _Pragma("unroll")                                                  \
            for (int r = 0; r < 4; r++) c[i][n][r] = 0.f;                      \
    const int NS = K >> 6;                                                     \
    auto issue = [&](int s, int bufi) {                                        \
        const int kb   = s << 6;                                               \
        const u32 base = shb + (u32)bufi * (2 * GSTG_H * 2);                   \
        const u32 ab   = base;                                                 \
        const u32 bb   = base + GSTG_H * 2;                                    \
        _Pragma("unroll")                                                      \
        for (int j = 0; j < 4; j++) {                                          \
            const int r = l_r + j * 32;                                        \
            cp16(ab + (u32)(r * 72 + l_c8) * 2,                                \
                 &A[(size_t)(row0 + r) * K + kb + l_c8]);                      \
            cp16(bb + (u32)(r * 72 + l_c8) * 2,                                \
                 &B[(size_t)(col0 + r) * K + kb + l_c8]);                      \
        }                                                                      \
        CP_COMMIT();                                                           \
    };                                                                         \
    issue(0, 0);                                                               \
    if (NS > 1) issue(1, 1);                                                   \
    int buf = 0;                                                               \
    for (int s = 0; s < NS; s++) {                                             \
        if (s + 1 < NS) { CP_WAIT(1); } else { CP_WAIT(0); }                   \
        __syncthreads();                                                       \
        if (s + 2 < NS) {                                                      \
            int ib = buf + 2; if (ib >= 3) ib -= 3;                            \
            issue(s + 2, ib);                                                  \
        }                                                                      \
        const u32 asb = shb + (u32)buf * (2 * GSTG_H * 2) + a_loff;            \
        const u32 bsb = shb + (u32)buf * (2 * GSTG_H * 2) + GSTG_H * 2         \
                        + b_loff;                                              \
        _Pragma("unroll")                                                      \
        for (int kt = 0; kt < 4; kt++) {                                       \
            uint4 af[4];                                                       \
            _Pragma("unroll")                                                  \
            for (int mt = 0; mt < 4; mt++) {                                   \
                u32 aq[4];                                                     \
                ldsm4(aq, asb + (u32)(((wm * 64 + mt * 16) * 72                \
                                       + kt * 16) * 2));                       \
                af[mt] = make_uint4(aq[0], aq[1], aq[2], aq[3]);               \
            }                                                                  \
            u32 bf[4][2];                                                      \
            _Pragma("unroll")                                                  \
            for (int pr = 0; pr < 2; pr++) {                                   \
                u32 bq[4];                                                     \
                ldsm4(bq, bsb + (u32)(((wn * 32 + pr * 16) * 72                \
                                       + kt * 16) * 2));                       \
                bf[2 * pr][0]     = bq[0]; bf[2 * pr][1]     = bq[1];          \
                bf[2 * pr + 1][0] = bq[2]; bf[2 * pr + 1][1] = bq[3];          \
            }                                                                  \
            _Pragma("unroll")                                                  \
            for (int mt = 0; mt < 4; mt++)                                     \
                _Pragma("unroll")                                              \
                for (int nt = 0; nt < 4; nt++)                                 \
                    mma_f16(c[mt][nt], af[mt], bf[nt][0], bf[nt][1]);          \
        }                                                                      \
        buf = (buf == 2) ? 0 : buf + 1;                                        \
    }                                                                          \
    _Pragma("unroll")                                                          \
    for (int mt = 0; mt < 4; mt++) {                                           \
        const int row = row0 + wm * 64 + mt * 16 + g;                          \
        _Pragma("unroll")                                                      \
        for (int nt = 0; nt < 4; nt++) {                                       \
            const int col = col0 + wn * 32 + nt * 8 + 2 * t;                   \
            C_STORE                                                            \
        }                                                                      \
    }

__global__ void __launch_bounds__(256, 2) hgemm(const __half* __restrict__ A,
                                                const __half* __restrict__ B,
                                                float* __restrict__ C,
                                                int M, int N, int K) {
    HGEMM_BODY(
        *(float2*)&C[(size_t)row * N + col] =
            make_float2(c[mt][nt][0], c[mt][nt][1]);
        *(float2*)&C[(size_t)(row + 8) * N + col] =
            make_float2(c[mt][nt][2], c[mt][nt][3]);
    )
}

__global__ void __launch_bounds__(256, 2) hgemm_h(const __half* __restrict__ A,
                                                  const __half* __restrict__ B,
                                                  __half* __restrict__ C,
                                                  int M, int N, int K) {
    HGEMM_BODY(
        *(u32*)&C[(size_t)row * N + col]       = f2h2(c[mt][nt][0], c[mt][nt][1]);
        *(u32*)&C[(size_t)(row + 8) * N + col] = f2h2(c[mt][nt][2], c[mt][nt][3]);
    )
}

// ---------------- RMSNorm + RoPE, prefetched loads (MLP=3) ------------------
// warp w: Q-unit w, Q-unit w+8, then K-unit (w<4) or V-unit (w>=4).
__global__ void __launch_bounds__(256) norm_rope_kernel(
    const __half* __restrict__ qkv,
    const float* __restrict__ qw, const float* __restrict__ kw,
    __half* __restrict__ qout,
    float*  __restrict__ kout,  float* __restrict__ vout,
    __half* __restrict__ khalf, __half* __restrict__ vhalf)
{
    const int s = blockIdx.x;
    const int w = threadIdx.x >> 5;
    const int l = threadIdx.x & 31;
    const int c = l * 4;
    const __half* row = qkv + (size_t)s * QKV_N;

    // ---- issue ALL loads up front (MLP=3 + weights + rope tables) ----
    const uint2 hq0 = *(const uint2*)&row[w * HDIM + c];
    const uint2 hq1 = *(const uint2*)&row[(w + 8) * HDIM + c];
    const uint2 hkv = *(const uint2*)&row[(w < 4 ? 2048 + w * HDIM
                                                 : 2560 + (w - 4) * HDIM) + c];
    const float4 qwv = *(const float4*)&qw[c];
    const float4 kwv = *(const float4*)&kw[c];
    const float4 cs  = *(const float4*)&g_rcos[s * 64 + (c & 63)];
    const float4 sn  = *(const float4*)&g_rsin[s * 64 + (c & 63)];
    const float cc[4] = {cs.x, cs.y, cs.z, cs.w};
    const float ss[4] = {sn.x, sn.y, sn.z, sn.w};

    // ---- V path (warps 4..7): pure copy ----
    if (w >= 4) {
        const int kv = w - 4;
        __half2 h0 = *(__half2*)&hkv.x, h1 = *(__half2*)&hkv.y;
        float2 a = __half22float2(h0), b2 = __half22float2(h1);
        *(float4*)&vout[((size_t)kv * SEQ + s) * HDIM + c] =
            make_float4(a.x, a.y, b2.x, b2.y);
        *(uint2*)&vhalf[((size_t)kv * SEQ + s) * HDIM + c] = hkv;
    }

    // ---- norm + rope helper over prefetched data ----
    auto nr = [&](uint2 hv, const float4& wv, float out[4]) {
        __half2 h0 = *(__half2*)&hv.x, h1 = *(__half2*)&hv.y;
        float2 a = __half22float2(h0), b2 = __half22float2(h1);
        float v0 = a.x, v1 = a.y, v2 = b2.x, v3 = b2.y;
        float sq = v0 * v0 + v1 * v1 + v2 * v2 + v3 * v3;
#pragma unroll
        for (int off = 16; off > 0; off >>= 1)
            sq += __shfl_xor_sync(0xffffffffu, sq, off);
        const float inv = rsqrtf(sq * (1.0f / HDIM) + 1e-6f);
        float xn[4] = {wv.x * v0 * inv, wv.y * v1 * inv,
                       wv.z * v2 * inv, wv.w * v3 * inv};
        float pr[4];
#pragma unroll
        for (int i = 0; i < 4; i++)
            pr[i] = __shfl_xor_sync(0xffffffffu, xn[i], 16);
#pragma unroll
        for (int i = 0; i < 4; i++)
            out[i] = (l < 16) ? (xn[i] * cc[i] - pr[i] * ss[i])
                              : (xn[i] * cc[i] + pr[i] * ss[i]);
    };

    float o0[4], o1[4];
    nr(hq0, qwv, o0);
    nr(hq1, qwv, o1);
    *(uint2*)&qout[((size_t)w * SEQ + s) * HDIM + c] =
        make_uint2(f2h2(o0[0] * QSCL, o0[1] * QSCL),
                   f2h2(o0[2] * QSCL, o0[3] * QSCL));
    *(uint2*)&qout[((size_t)(w + 8) * SEQ + s) * HDIM + c] =
        make_uint2(f2h2(o1[0] * QSCL, o1[1] * QSCL),
                   f2h2(o1[2] * QSCL, o1[3] * QSCL));

    // ---- K path (warps 0..3) ----
    if (w < 4) {
        float ok[4];
        nr(hkv, kwv, ok);
        *(float4*)&kout[((size_t)w * SEQ + s) * HDIM + c] =
            make_float4(ok[0], ok[1], ok[2], ok[3]);
        *(uint2*)&khalf[((size_t)w * SEQ + s) * HDIM + c] =
            make_uint2(f2h2(ok[0], ok[1]), f2h2(ok[2], ok[3]));
    }
}

// ---------------- Flash attention: BM=128, BN=128, register-P FA2 ----------
// (round-14 verified form)
#define FQ_LD 136
#define KS_LD 136
#define VS_LD 136
#define KS_TILE_H (128 * KS_LD)
#define VS_TILE_H (128 * VS_LD)
#define FLASH_SMEM_HALVES (128*FQ_LD + 2*KS_TILE_H + 2*VS_TILE_H)
#define FLASH_SMEM_BYTES  (FLASH_SMEM_HALVES * 2)

__global__ void __launch_bounds__(256, 1) flash_f16(
    const __half* __restrict__ Q,
    const __half* __restrict__ Kh,
    const __half* __restrict__ Vh,
    __half* __restrict__ ctx)
{
    extern __shared__ __half smh[];
    __half* Qs = smh;                          // [128][136]
    __half* Ks = Qs + 128 * FQ_LD;             // 2 x [128][136]
    __half* Vs = Ks + 2 * KS_TILE_H;           // 2 x [128][136]

    const u32 ksb0 = smem_u32(Ks);
    const u32 vsb0 = smem_u32(Vs);

    const int tid  = threadIdx.x;
    const int lane = tid & 31;
    const int w    = tid >> 5;
    const int g    = lane >> 2;
    const int t    = lane & 3;
    const int qt   = (gridDim.x - 1) - blockIdx.x;   // big tiles first
    const int head = blockIdx.y;
    const int kv   = head / GROUP;
    const int q0   = qt * 128;
    const int rw   = w * 16;

    const u32 k_off = ((u32)(((lane >> 4) & 1) * 8 + (lane & 7)) * KS_LD
                       + (u32)(((lane >> 3) & 1) * 8)) * 2;
    const u32 v_off = ((u32)(((lane >> 3) & 1) * 8 + (lane & 7)) * VS_LD
                       + (u32)((lane >> 4) * 8)) * 2;

    const __half* kg = Kh + (size_t)kv * SEQ * HDIM;
    const __half* vg = Vh + (size_t)kv * SEQ * HDIM;
    const int l_r  = tid >> 4;
    const int l_c8 = (tid & 15) * 8;

    const int njt = qt + 1;

    auto issue = [&](int jt) {
        const int k0 = jt * 128;
        const u32 kd = ksb0 + (u32)(jt & 1) * (KS_TILE_H * 2);
        const u32 vd = vsb0 + (u32)(jt & 1) * (VS_TILE_H * 2);
#pragma unroll
        for (int j = 0; j < 8; j++) {
            const int r = l_r + j * 16;
            cp16(kd + (u32)(r * KS_LD + l_c8) * 2,
                 kg + (size_t)(k0 + r) * HDIM + l_c8);
            cp16(vd + (u32)(r * VS_LD + l_c8) * 2,
                 vg + (size_t)(k0 + r) * HDIM + l_c8);
        }
        CP_COMMIT();
    };

    issue(0);
    if (njt > 1) issue(1);
    {
        const uint4* src = (const uint4*)(Q + ((size_t)head * SEQ + q0) * HDIM);
#pragma unroll
        for (int j = 0; j < 8; j++) {
            const int i = tid + j * 256;
            const int r = i >> 4, c8 = (i & 15) * 8;
            *(uint4*)&Qs[r * FQ_LD + c8] = src[r * 16 + (i & 15)];
        }
    }
    __syncthreads();

    uint4 af[8];
#pragma unroll
    for (int kt = 0; kt < 8; kt++) {
        af[kt].x = *(const u32*)&Qs[(rw + g)     * FQ_LD + kt * 16 + 2 * t];
        af[kt].y = *(const u32*)&Qs[(rw + g + 8) * FQ_LD + kt * 16 + 2 * t];
        af[kt].z = *(const u32*)&Qs[(rw + g)     * FQ_LD + kt * 16 + 2 * t + 8];
        af[kt].w = *(const u32*)&Qs[(rw + g + 8) * FQ_LD + kt * 16 + 2 * t + 8];
    }

    float o[16][4];
#pragma unroll
    for (int n = 0; n < 16; n++)
#pragma unroll
        for (int r = 0; r < 4; r++) o[n][r] = 0.f;
    float mA = -INFINITY, mB = -INFINITY, lA = 0.f, lB = 0.f;

    const int rowA = q0 + rw + g;
    const int rowB = rowA + 8;

    for (int jt = 0; jt < njt; jt++) {
        const int k0 = jt * 128;
        if (jt + 1 < njt) { CP_WAIT(1); } else { CP_WAIT(0); }
        __syncthreads();

        const u32 kfb = ksb0 + (u32)(jt & 1) * (KS_TILE_H * 2) + k_off;
        const u32 vfb = vsb0 + (u32)(jt & 1) * (VS_TILE_H * 2) + v_off;

        // ---- S = Q @ K^T  (scores already in log2 domain via QSCL) ----
        float s[16][4];
#pragma unroll
        for (int n = 0; n < 16; n++)
#pragma unroll
            for (int r = 0; r < 4; r++) s[n][r] = 0.f;
#pragma unroll
        for (int kt = 0; kt < 8; kt++) {
#pragma unroll
            for (int np = 0; np < 8; np++) {
                u32 bf[4];
                ldsm4(bf, kfb + (u32)(np * 16 * KS_LD + kt * 16) * 2);
                mma_f16(s[2 * np],     af[kt], bf[0], bf[1]);
                mma_f16(s[2 * np + 1], af[kt], bf[2], bf[3]);
            }
        }

        // ---- causal mask (diag tile only) ----
        if (jt == qt) {
#pragma unroll
            for (int nt = 0; nt < 16; nt++) {
                const int c0 = k0 + nt * 8 + 2 * t;
                const int c1 = c0 + 1;
                if (c0 > rowA) s[nt][0] = -1e30f;
                if (c1 > rowA) s[nt][1] = -1e30f;
                if (c0 > rowB) s[nt][2] = -1e30f;
                if (c1 > rowB) s[nt][3] = -1e30f;
            }
        }

        // ---- online softmax (base-2); P packed straight into A-fragments ----
        float mxA = -1e30f, mxB = -1e30f;
#pragma unroll
        for (int nt = 0; nt < 16; nt++) {
            mxA = fmaxf(mxA, fmaxf(s[nt][0], s[nt][1]));
            mxB = fmaxf(mxB, fmaxf(s[nt][2], s[nt][3]));
        }
        mxA = fmaxf(mxA, __shfl_xor_sync(0xffffffffu, mxA, 1));
        mxA = fmaxf(mxA, __shfl_xor_sync(0xffffffffu, mxA, 2));
        mxB = fmaxf(mxB, __shfl_xor_sync(0xffffffffu, mxB, 1));
        mxB = fmaxf(mxB, __shfl_xor_sync(0xffffffffu, mxB, 2));

        const float mnA = fmaxf(mA, mxA);
        const float mnB = fmaxf(mB, mxB);
        const float cA  = exp2f(mA - mnA);
        const float cB  = exp2f(mB - mnB);

        uint4 pf8[8];
        float sA = 0.f, sB = 0.f;
#pragma unroll
        for (int kt = 0; kt < 8; kt++) {
#pragma unroll
            for (int h = 0; h < 2; h++) {
                const int nt = 2 * kt + h;
                const float p0 = exp2f(s[nt][0] - mnA);
                const float p1 = exp2f(s[nt][1] - mnA);
                const float p2 = exp2f(s[nt][2] - mnB);
                const float p3 = exp2f(s[nt][3] - mnB);
                sA += p0 + p1;  sB += p2 + p3;
                if (h == 0) { pf8[kt].x = f2h2(p0, p1); pf8[kt].y = f2h2(p2, p3); }
                else        { pf8[kt].z = f2h2(p0, p1); pf8[kt].w = f2h2(p2, p3); }
            }
        }
        sA += __shfl_xor_sync(0xffffffffu, sA, 1);
        sA += __shfl_xor_sync(0xffffffffu, sA, 2);
        sB += __shfl_xor_sync(0xffffffffu, sB, 1);
        sB += __shfl_xor_sync(0xffffffffu, sB, 2);

        lA = lA * cA + sA;  lB = lB * cB + sB;
        mA = mnA;           mB = mnB;
#pragma unroll
        for (int nt = 0; nt < 16; nt++) {
            o[nt][0] *= cA;  o[nt][1] *= cA;
            o[nt][2] *= cB;  o[nt][3] *= cB;
        }

        // ---- O += P @ V (P from registers) ----
#pragma unroll
        for (int kt = 0; kt < 8; kt++) {
#pragma unroll
            for (int np = 0; np < 8; np++) {
                u32 bf[4];
                ldsm4t(bf, vfb + (u32)(kt * 16 * VS_LD + np * 16) * 2);
                mma_f16(o[2 * np],     pf8[kt], bf[0], bf[1]);
                mma_f16(o[2 * np + 1], pf8[kt], bf[2], bf[3]);
            }
        }
        __syncthreads();
        if (jt + 2 < njt) issue(jt + 2);
    }

    const float iA = 1.0f / lA;
    const float iB = 1.0f / lB;
#pragma unroll
    for (int nt = 0; nt < 16; nt++) {
        const int col = head * HDIM + nt * 8 + 2 * t;
        *(u32*)&ctx[(size_t)rowA * EMB + col] = f2h2(o[nt][0] * iA, o[nt][1] * iA);
        *(u32*)&ctx[(size_t)rowB * EMB + col] = f2h2(o[nt][2] * iB, o[nt][3] * iB);
    }
}

// ---------------- launch ----------------------------------------------------
extern "C" void kernel_launch(void* const* d_in, const int* in_sizes, int n_in,
                              void* d_out, int out_size) {
    const float* x   = (const float*)d_in[0];
    const int*   pos = (const int*)  d_in[1];
    // d_in[2] = attn_mask (pure causal) -- analytic
    const float* Wq  = (const float*)d_in[3];
    const float* Wk  = (const float*)d_in[4];
    const float* Wv  = (const float*)d_in[5];
    const float* Wo  = (const float*)d_in[6];
    const float* qw  = (const float*)d_in[7];
    const float* kw  = (const float*)d_in[8];

    float* out  = (float*)d_out;
    float* kout = out  + (size_t)SEQ * EMB;
    float* vout = kout + (size_t)NKV * SEQ * HDIM;

    __half *qkvh, *xh, *qh, *kh, *vh, *ctxh, *wqkvt, *wot;
    cudaGetSymbolAddress((void**)&qkvh,  g_qkvh);
    cudaGetSymbolAddress((void**)&xh,    g_xh);
    cudaGetSymbolAddress((void**)&qh,    g_qh);
    cudaGetSymbolAddress((void**)&kh,    g_kh);
    cudaGetSymbolAddress((void**)&vh,    g_vh);
    cudaGetSymbolAddress((void**)&ctxh,  g_ctxh);
    cudaGetSymbolAddress((void**)&wqkvt, g_wqkvt);
    cudaGetSymbolAddress((void**)&wot,   g_wot);

    cudaFuncSetAttribute(hgemm,
                         cudaFuncAttributeMaxDynamicSharedMemorySize, GEMM_SMEM_BYTES);
    cudaFuncSetAttribute(hgemm_h,
                         cudaFuncAttributeMaxDynamicSharedMemorySize, GEMM_SMEM_BYTES);
    cudaFuncSetAttribute(flash_f16,
                         cudaFuncAttributeMaxDynamicSharedMemorySize, FLASH_SMEM_BYTES);

    // 0) all prep in one launch
    prep_kernel<<<PREP_BLOCKS, 256>>>(x, Wq, Wk, Wv, Wo, pos, xh, wqkvt, wot);

    // 1) fused QKV projection (half output)
    hgemm_h<<<dim3(QKV_N / 128, SEQ / 128), 256, GEMM_SMEM_BYTES>>>(
        xh, wqkvt, qkvh, SEQ, QKV_N, EMB);

    // 2) rmsnorm + rope (prefetched, MLP=3)
    norm_rope_kernel<<<SEQ, 256>>>(qkvh, qw, kw, qh, kout, vout, kh, vh);

    // 3) causal flash attention (register-P)
    flash_f16<<<dim3(SEQ / 128, NHEADS), 256, FLASH_SMEM_BYTES>>>(qh, kh, vh, ctxh);

    // 4) output projection
    hgemm<<<dim3(EMB / 128, SEQ / 128), 256, GEMM_SMEM_BYTES>>>(
        ctxh, wot, out, SEQ, EMB, EMB);
}